// round 13
// baseline (speedup 1.0000x reference)
#include <cuda_runtime.h>
#include <cuda_fp16.h>
#include <cstdint>

// ---------------- problem / tiling ----------------
#define MM 8192
#define NN 11008
#define KK 4096
#define BM 128
#define BN 128
#define BK 64
#define STAGES 3
#define THREADS 128
#define KSTEPS (KK / BK)     // 64
#define MTILES (MM / BM)     // 64
#define NTILES (NN / BN)     // 86
#define GROUP_M 8

// smem: per stage [A 16KB][B 16KB]
#define ASTG_B (BM * BK * 2)             // 16384
#define BSTG_B (BN * BK * 2)             // 16384
#define STG_B (ASTG_B + BSTG_B)          // 32768
#define SMEM_B (STAGES * STG_B)          // 98304 (2 CTAs/SM)

// ---------------- fp16 scratch (allocation-free __device__ globals) ----------------
__device__ __half2 g_xh[(size_t)MM * KK / 2];   // 64 MB
__device__ __half2 g_wh[(size_t)NN * KK / 2];   // 86 MB

// ---------------- PTX helpers (base sm_103 target: no tcgen05/TMA) ----------------
__device__ __forceinline__ uint32_t smem_u32(const void* p) {
    uint32_t a;
    asm("{ .reg .u64 t; cvta.to.shared.u64 t, %1; cvt.u32.u64 %0, t; }" : "=r"(a) : "l"(p));
    return a;
}

#define CP_ASYNC16(dst, src) \
    asm volatile("cp.async.cg.shared.global [%0], [%1], 16;" :: "r"(dst), "l"(src))
#define CP_COMMIT() asm volatile("cp.async.commit_group;" ::: "memory")
#define CP_WAIT1()  asm volatile("cp.async.wait_group 1;" ::: "memory")
#define CP_WAIT0()  asm volatile("cp.async.wait_group 0;" ::: "memory")

#define LDSM_X4(r0, r1, r2, r3, addr) \
    asm volatile("ldmatrix.sync.aligned.m8n8.x4.shared.b16 {%0,%1,%2,%3}, [%4];" \
        : "=r"(r0), "=r"(r1), "=r"(r2), "=r"(r3) : "r"(addr))

#define MMA16816(c, a, b0, b1) \
    asm volatile("mma.sync.aligned.m16n8k16.row.col.f32.f16.f16.f32 " \
        "{%0,%1,%2,%3}, {%4,%5,%6,%7}, {%8,%9}, {%0,%1,%2,%3};" \
        : "+f"((c)[0]), "+f"((c)[1]), "+f"((c)[2]), "+f"((c)[3]) \
        : "r"((a)[0]), "r"((a)[1]), "r"((a)[2]), "r"((a)[3]), "r"(b0), "r"(b1))

// ---------------- conversion kernels ----------------
__global__ void cvt_x_kernel(const float4* __restrict__ x) {
    int i = blockIdx.x * blockDim.x + threadIdx.x;   // exact: MM*KK/4 threads
    float4 v = x[i];
    g_xh[2 * i]     = __floats2half2_rn(v.x, v.y);
    g_xh[2 * i + 1] = __floats2half2_rn(v.z, v.w);
}
__global__ void cvt_w_kernel(const int4* __restrict__ w) {
    int i = blockIdx.x * blockDim.x + threadIdx.x;   // exact: NN*KK/4 threads
    int4 v = w[i];
    g_wh[2 * i]     = __halves2half2(__int2half_rn(v.x), __int2half_rn(v.y));
    g_wh[2 * i + 1] = __halves2half2(__int2half_rn(v.z), __int2half_rn(v.w));
}

// ---------------- GEMM: 128 threads, warp grid 2(M) x 2(N), warp tile 64x64 ----------------
__global__ __launch_bounds__(THREADS, 2) void gemm_f16_kernel(
    const float* __restrict__ scale, float* __restrict__ out)
{
    extern __shared__ __align__(1024) char smem[];
    const uint32_t sb = smem_u32(smem);
    const int tid = threadIdx.x;
    const int lane = tid & 31;
    const int wid = tid >> 5;
    const int warp_m = wid & 1;       // 0..1 -> M offset 64*warp_m
    const int warp_n = wid >> 1;      // 0..1 -> N offset 64*warp_n

    // GROUP_M tile swizzle for L2 locality
    const int bid = blockIdx.x;
    const int rem = bid % (GROUP_M * NTILES);
    const int mt = (bid / (GROUP_M * NTILES)) * GROUP_M + (rem % GROUP_M);
    const int nt = rem / GROUP_M;
    const int mbase = mt * BM;
    const int nbase = nt * BN;

    const __half* gA = (const __half*)g_xh;
    const __half* gB = (const __half*)g_wh;

    // ---- stage loader: A 1024 + B 1024 16B-chunks over 128 threads ----
    auto load_stage = [&](int s, int ks) {
        const uint32_t abase = sb + s * STG_B;
        const uint32_t bbase = abase + ASTG_B;
        const int row = tid >> 3, ch = tid & 7;   // row 0..15
#pragma unroll
        for (int j = 0; j < 8; j++) {
            int r = row + j * 16;
            uint32_t sa = abase + r * 128 + ((ch ^ (r & 7)) << 4);
            CP_ASYNC16(sa, gA + ((size_t)(mbase + r) * KK + ks * BK + ch * 8));
        }
#pragma unroll
        for (int j = 0; j < 8; j++) {
            int r = row + j * 16;
            uint32_t sa = bbase + r * 128 + ((ch ^ (r & 7)) << 4);
            CP_ASYNC16(sa, gB + ((size_t)(nbase + r) * KK + ks * BK + ch * 8));
        }
    };

    float acc[4][8][4];
#pragma unroll
    for (int mf = 0; mf < 4; mf++)
#pragma unroll
        for (int nf = 0; nf < 8; nf++)
#pragma unroll
            for (int q = 0; q < 4; q++) acc[mf][nf][q] = 0.f;

    const int lrow = lane & 15;
    const int lch = lane >> 4;

    // ---- fragment load for one kk (K=16 slice): 4 A-frags + 4 B-groups ----
    auto load_frags = [&](uint32_t abase, uint32_t bbase, int kk,
                          uint32_t (*af)[4], uint32_t (*bf)[4]) {
        const int ch = kk * 2 + lch;
#pragma unroll
        for (int mf = 0; mf < 4; mf++) {
            int r = warp_m * 64 + mf * 16 + lrow;
            uint32_t addr = abase + r * 128 + ((ch ^ (r & 7)) << 4);
            LDSM_X4(af[mf][0], af[mf][1], af[mf][2], af[mf][3], addr);
        }
#pragma unroll
        for (int g = 0; g < 4; g++) {
            int r = warp_n * 64 + g * 16 + lrow;
            uint32_t addr = bbase + r * 128 + ((ch ^ (r & 7)) << 4);
            LDSM_X4(bf[g][0], bf[g][1], bf[g][2], bf[g][3], addr);
        }
    };

    // ---- one K-step (BK=64), fragment double-buffered ----
    auto compute_stage = [&](int s) {
        const uint32_t abase = sb + s * STG_B;
        const uint32_t bbase = abase + ASTG_B;
        uint32_t af[2][4][4], bf[2][4][4];
        load_frags(abase, bbase, 0, af[0], bf[0]);
#pragma unroll
        for (int kk = 0; kk < 4; kk++) {
            const int cur = kk & 1, nxt = cur ^ 1;
            if (kk < 3) load_frags(abase, bbase, kk + 1, af[nxt], bf[nxt]);
#pragma unroll
            for (int mf = 0; mf < 4; mf++)
#pragma unroll
                for (int g = 0; g < 4; g++) {
                    MMA16816(acc[mf][g * 2],     af[cur][mf], bf[cur][g][0], bf[cur][g][2]);
                    MMA16816(acc[mf][g * 2 + 1], af[cur][mf], bf[cur][g][1], bf[cur][g][3]);
                }
        }
    };

    // prologue: 2 stages in flight
    load_stage(0, 0); CP_COMMIT();
    load_stage(1, 1); CP_COMMIT();

    // main loop over ks = 0..62 (21 blocks of 3: static stage indices).
    // Loads issued BEFORE compute so each fill overlaps ~2 compute phases.
#pragma unroll 1
    for (int kb = 0; kb < KSTEPS - 1; kb += STAGES) {
#pragma unroll
        for (int u = 0; u < STAGES; u++) {
            const int ks = kb + u;
            CP_WAIT1();
            __syncthreads();
            if (ks + 2 < KSTEPS) load_stage((ks + 2) % STAGES, ks + 2);
            CP_COMMIT();
            compute_stage(u);
        }
    }
    // tail: ks = 63 -> stage 0 (wait_group 0: trailing empty groups retire instantly)
    CP_WAIT0();
    __syncthreads();
    compute_stage(0);

    // ---- epilogue: direct float2 stores, scale applied ----
    const float sc = __ldg(scale);
#pragma unroll
    for (int mf = 0; mf < 4; mf++) {
        const int r0 = mbase + warp_m * 64 + mf * 16 + (lane >> 2);
#pragma unroll
        for (int nf = 0; nf < 8; nf++) {
            const int c = nbase + warp_n * 64 + nf * 8 + (lane & 3) * 2;
            float2 v0 = make_float2(acc[mf][nf][0] * sc, acc[mf][nf][1] * sc);
            float2 v1 = make_float2(acc[mf][nf][2] * sc, acc[mf][nf][3] * sc);
            *(float2*)&out[(size_t)r0 * NN + c] = v0;
            *(float2*)&out[(size_t)(r0 + 8) * NN + c] = v1;
        }
    }
}

// ---------------- host ----------------
extern "C" void kernel_launch(void* const* d_in, const int* in_sizes, int n_in,
                              void* d_out, int out_size) {
    const float* x = (const float*)d_in[0];
    const int* w = (const int*)d_in[1];
    const float* scale = (const float*)d_in[2];
    float* out = (float*)d_out;

    cvt_x_kernel<<<(int)((size_t)MM * KK / 4 / 256), 256>>>((const float4*)x);
    cvt_w_kernel<<<(int)((size_t)NN * KK / 4 / 256), 256>>>((const int4*)w);

    static bool attr_set = false;
    if (!attr_set) {
        cudaFuncSetAttribute(gemm_f16_kernel,
                             cudaFuncAttributeMaxDynamicSharedMemorySize, SMEM_B);
        attr_set = true;
    }
    gemm_f16_kernel<<<MTILES * NTILES, THREADS, SMEM_B>>>(scale, out);
}

// round 15
// speedup vs baseline: 1.1366x; 1.1366x over previous
#include <cuda_runtime.h>
#include <cuda_fp16.h>
#include <cuda.h>
#include <cstdint>

// ---------------- problem / tiling ----------------
#define MM 8192
#define NN 11008
#define KK 4096
#define BM 128
#define BN 128
#define BK 64
#define STAGES 3
#define THREADS 256
#define KSTEPS (KK / BK)     // 64
#define MTILES (MM / BM)     // 64
#define NTILES (NN / BN)     // 86
#define GROUP_M 8

// smem: [0,1024) barriers, then 3 stages of [A 16KB][B 16KB]
#define OFF_FULL 64
#define OFF_TILE 1024
#define ASTG_B (BM * BK * 2)             // 16384
#define STG_B (2 * ASTG_B)               // 32768
#define SMEM_B (OFF_TILE + STAGES * STG_B)   // 99328 (2 CTAs/SM)

// ---------------- fp16 scratch (allocation-free __device__ globals) ----------------
__device__ __half2 g_xh[(size_t)MM * KK / 2];   // 64 MB
__device__ __half2 g_wh[(size_t)NN * KK / 2];   // 86 MB

// ---------------- PTX helpers (base sm_103: TMA + mbarrier OK, no tcgen05) ----------------
__device__ __forceinline__ uint32_t smem_u32(const void* p) {
    uint32_t a;
    asm("{ .reg .u64 t; cvta.to.shared.u64 t, %1; cvt.u32.u64 %0, t; }" : "=r"(a) : "l"(p));
    return a;
}

#define MBARRIER_INIT(addr, cnt) \
    asm volatile("mbarrier.init.shared.b64 [%0], %1;" :: "r"(addr), "r"((uint32_t)(cnt)) : "memory")
#define MBARRIER_EXPECT_TX(addr, bytes) \
    asm volatile("mbarrier.arrive.expect_tx.shared.b64 _, [%0], %1;" :: "r"(addr), "r"((uint32_t)(bytes)) : "memory")

#define MBARRIER_WAIT_PARITY(mbar_addr, phase_parity) do { \
    uint32_t _mbar = (uint32_t)(mbar_addr); \
    uint32_t _parity = (uint32_t)(phase_parity); \
    uint32_t _done; \
    asm volatile( \
        "{\n\t.reg .pred p;\n\t" \
        "mbarrier.try_wait.parity.acquire.cta.shared::cta.b64 p, [%1], %2;\n\t" \
        "selp.b32 %0, 1, 0, p;\n\t}" \
        : "=r"(_done) : "r"(_mbar), "r"(_parity) : "memory"); \
    if (!_done) { \
        asm volatile( \
            "{\n\t.reg .pred P1;\n\t" \
            "WAIT_LOOP_%=:\n\t" \
            "mbarrier.try_wait.parity.acquire.cta.shared::cta.b64 P1, [%0], %1, 0x989680;\n\t" \
            "@P1 bra.uni WAIT_DONE_%=;\n\t" \
            "bra.uni WAIT_LOOP_%=;\n\t" \
            "WAIT_DONE_%=:\n\t}" \
            :: "r"(_mbar), "r"(_parity) : "memory"); \
    } \
} while(0)

#define TMA2D(dst, map, c0, c1, bar) \
    asm volatile( \
        "cp.async.bulk.tensor.2d.shared::cta.global.tile.mbarrier::complete_tx::bytes " \
        "[%0], [%1, {%2, %3}], [%4];" \
        :: "r"((uint32_t)(dst)), "l"(map), "r"((int32_t)(c0)), "r"((int32_t)(c1)), \
           "r"((uint32_t)(bar)) : "memory")

#define LDSM_X4(r0, r1, r2, r3, addr) \
    asm volatile("ldmatrix.sync.aligned.m8n8.x4.shared.b16 {%0,%1,%2,%3}, [%4];" \
        : "=r"(r0), "=r"(r1), "=r"(r2), "=r"(r3) : "r"(addr))

#define MMA16816(c, a, b0, b1) \
    asm volatile("mma.sync.aligned.m16n8k16.row.col.f32.f16.f16.f32 " \
        "{%0,%1,%2,%3}, {%4,%5,%6,%7}, {%8,%9}, {%0,%1,%2,%3};" \
        : "+f"((c)[0]), "+f"((c)[1]), "+f"((c)[2]), "+f"((c)[3]) \
        : "r"((a)[0]), "r"((a)[1]), "r"((a)[2]), "r"((a)[3]), "r"(b0), "r"(b1))

// ---------------- conversion kernels ----------------
__global__ void cvt_x_kernel(const float4* __restrict__ x) {
    int i = blockIdx.x * blockDim.x + threadIdx.x;   // exact: MM*KK/4 threads
    float4 v = x[i];
    g_xh[2 * i]     = __floats2half2_rn(v.x, v.y);
    g_xh[2 * i + 1] = __floats2half2_rn(v.z, v.w);
}
__global__ void cvt_w_kernel(const int4* __restrict__ w) {
    int i = blockIdx.x * blockDim.x + threadIdx.x;   // exact: NN*KK/4 threads
    int4 v = w[i];
    g_wh[2 * i]     = __halves2half2(__int2half_rn(v.x), __int2half_rn(v.y));
    g_wh[2 * i + 1] = __halves2half2(__int2half_rn(v.z), __int2half_rn(v.w));
}

// ---------------- GEMM: 256 threads, warp grid 4(M) x 2(N), warp tile 32x64 ----------------
// TMA fills (2 instructions/stage from tid 0) replace 2048 cp.async ops/stage.
__global__ __launch_bounds__(THREADS, 2) void gemm_f16_kernel(
    const __grid_constant__ CUtensorMap tmA,
    const __grid_constant__ CUtensorMap tmB,
    const float* __restrict__ scale,
    float* __restrict__ out)
{
    extern __shared__ __align__(1024) char smem[];
    const uint32_t sb = smem_u32(smem);
    const int tid = threadIdx.x;
    const int lane = tid & 31;
    const int wid = tid >> 5;
    const int warp_m = wid & 3;       // 0..3 -> M offset 32*warp_m
    const int warp_n = wid >> 2;      // 0..1 -> N offset 64*warp_n

    // GROUP_M tile swizzle for L2 locality
    const int bid = blockIdx.x;
    const int rem = bid % (GROUP_M * NTILES);
    const int mt = (bid / (GROUP_M * NTILES)) * GROUP_M + (rem % GROUP_M);
    const int nt = rem / GROUP_M;
    const int mbase = mt * BM;
    const int nbase = nt * BN;

    if (tid == 0) {
#pragma unroll
        for (int s = 0; s < STAGES; s++) MBARRIER_INIT(sb + OFF_FULL + 8 * s, 1);
    }
    __syncthreads();

    // TMA fill of stage s with K-step ks (A 16KB + B 16KB on one barrier)
    auto fill = [&](int s, int ks) {
        const uint32_t bar = sb + OFF_FULL + 8 * s;
        const uint32_t dst = sb + OFF_TILE + s * STG_B;
        MBARRIER_EXPECT_TX(bar, STG_B);
        TMA2D(dst, &tmA, ks * BK, mbase, bar);
        TMA2D(dst + ASTG_B, &tmB, ks * BK, nbase, bar);
    };

    float acc[2][8][4];
#pragma unroll
    for (int mf = 0; mf < 2; mf++)
#pragma unroll
        for (int nf = 0; nf < 8; nf++)
#pragma unroll
            for (int q = 0; q < 4; q++) acc[mf][nf][q] = 0.f;

    const int lrow = lane & 15;
    const int lch = lane >> 4;

    // TMA SW128 layout == r*128 + 16*(ch ^ (r&7)), identical to prior manual swizzle
    auto compute_stage = [&](int s) {
        const uint32_t abase = sb + OFF_TILE + s * STG_B;
        const uint32_t bbase = abase + ASTG_B;
#pragma unroll
        for (int kk = 0; kk < 4; kk++) {
            uint32_t a[2][4], br[4][4];
            const int ch = kk * 2 + lch;
#pragma unroll
            for (int mf = 0; mf < 2; mf++) {
                int r = warp_m * 32 + mf * 16 + lrow;
                uint32_t addr = abase + r * 128 + ((ch ^ (r & 7)) << 4);
                LDSM_X4(a[mf][0], a[mf][1], a[mf][2], a[mf][3], addr);
            }
#pragma unroll
            for (int g = 0; g < 4; g++) {
                int r = warp_n * 64 + g * 16 + lrow;
                uint32_t addr = bbase + r * 128 + ((ch ^ (r & 7)) << 4);
                LDSM_X4(br[g][0], br[g][1], br[g][2], br[g][3], addr);
            }
#pragma unroll
            for (int mf = 0; mf < 2; mf++)
#pragma unroll
                for (int g = 0; g < 4; g++) {
                    MMA16816(acc[mf][g * 2],     a[mf], br[g][0], br[g][2]);
                    MMA16816(acc[mf][g * 2 + 1], a[mf], br[g][1], br[g][3]);
                }
        }
    };

    // prologue: 2 stages in flight
    if (tid == 0) { fill(0, 0); fill(1, 1); }

    // main loop over ks = 0..62 (21 blocks of 3: static stage indices).
    // Refill of stage (ks+2)%3 == (ks-1)%3 is safe: the __syncthreads at iter
    // top guarantees all warps finished computing ks-1.
    // full[s] parity for use-index n = ks/3 is n&1 (constant per kb block).
#pragma unroll 1
    for (int kb = 0; kb < KSTEPS - 1; kb += STAGES) {
        const uint32_t par = (kb / STAGES) & 1;
#pragma unroll
        for (int u = 0; u < STAGES; u++) {
            const int ks = kb + u;
            __syncthreads();
            if (tid == 0 && ks + 2 < KSTEPS) fill((ks + 2) % STAGES, ks + 2);
            MBARRIER_WAIT_PARITY(sb + OFF_FULL + 8 * u, par);
            compute_stage(u);
        }
    }
    // tail: ks = 63 -> stage 0, use-index 21 -> parity 1
    __syncthreads();
    MBARRIER_WAIT_PARITY(sb + OFF_FULL, 1);
    compute_stage(0);

    // ---- epilogue: direct float2 stores, scale applied ----
    const float sc = __ldg(scale);
#pragma unroll
    for (int mf = 0; mf < 2; mf++) {
        const int r0 = mbase + warp_m * 32 + mf * 16 + (lane >> 2);
#pragma unroll
        for (int nf = 0; nf < 8; nf++) {
            const int c = nbase + warp_n * 64 + nf * 8 + (lane & 3) * 2;
            float2 v0 = make_float2(acc[mf][nf][0] * sc, acc[mf][nf][1] * sc);
            float2 v1 = make_float2(acc[mf][nf][2] * sc, acc[mf][nf][3] * sc);
            *(float2*)&out[(size_t)r0 * NN + c] = v0;
            *(float2*)&out[(size_t)(r0 + 8) * NN + c] = v1;
        }
    }
}

// ---------------- host ----------------
typedef CUresult (*tmap_fn_t)(CUtensorMap*, CUtensorMapDataType, cuuint32_t, void*,
    const cuuint64_t*, const cuuint64_t*, const cuuint32_t*, const cuuint32_t*,
    CUtensorMapInterleave, CUtensorMapSwizzle, CUtensorMapL2promotion,
    CUtensorMapFloatOOBfill);

static tmap_fn_t get_encoder() {
    void* fn = nullptr;
    cudaDriverEntryPointQueryResult st;
#if CUDART_VERSION >= 12050
    cudaGetDriverEntryPointByVersion("cuTensorMapEncodeTiled", &fn, 12000,
                                     cudaEnableDefault, &st);
#else
    cudaGetDriverEntryPoint("cuTensorMapEncodeTiled", &fn, cudaEnableDefault, &st);
#endif
    return (tmap_fn_t)fn;
}

extern "C" void kernel_launch(void* const* d_in, const int* in_sizes, int n_in,
                              void* d_out, int out_size) {
    const float* x = (const float*)d_in[0];
    const int* w = (const int*)d_in[1];
    const float* scale = (const float*)d_in[2];
    float* out = (float*)d_out;

    cvt_x_kernel<<<(int)((size_t)MM * KK / 4 / 256), 256>>>((const float4*)x);
    cvt_w_kernel<<<(int)((size_t)NN * KK / 4 / 256), 256>>>((const int4*)w);

    void *xh = nullptr, *wh = nullptr;
    cudaGetSymbolAddress(&xh, g_xh);
    cudaGetSymbolAddress(&wh, g_wh);

    tmap_fn_t enc = get_encoder();
    CUtensorMap tmA, tmB;
    {
        cuuint64_t dims[2] = {KK, MM};
        cuuint64_t str[1]  = {KK * 2};
        cuuint32_t box[2]  = {BK, BM};      // 64 halves = 128B = SW128 atom width
        cuuint32_t es[2]   = {1, 1};
        enc(&tmA, CU_TENSOR_MAP_DATA_TYPE_UINT16, 2, xh, dims, str, box, es,
            CU_TENSOR_MAP_INTERLEAVE_NONE, CU_TENSOR_MAP_SWIZZLE_128B,
            CU_TENSOR_MAP_L2_PROMOTION_L2_128B, CU_TENSOR_MAP_FLOAT_OOB_FILL_NONE);
    }
    {
        cuuint64_t dims[2] = {KK, NN};
        cuuint64_t str[1]  = {KK * 2};
        cuuint32_t box[2]  = {BK, BM};
        cuuint32_t es[2]   = {1, 1};
        enc(&tmB, CU_TENSOR_MAP_DATA_TYPE_UINT16, 2, wh, dims, str, box, es,
            CU_TENSOR_MAP_INTERLEAVE_NONE, CU_TENSOR_MAP_SWIZZLE_128B,
            CU_TENSOR_MAP_L2_PROMOTION_L2_128B, CU_TENSOR_MAP_FLOAT_OOB_FILL_NONE);
    }

    static bool attr_set = false;
    if (!attr_set) {
        cudaFuncSetAttribute(gemm_f16_kernel,
                             cudaFuncAttributeMaxDynamicSharedMemorySize, SMEM_B);
        attr_set = true;
    }
    gemm_f16_kernel<<<MTILES * NTILES, THREADS, SMEM_B>>>(tmA, tmB, scale, out);
}